// round 13
// baseline (speedup 1.0000x reference)
#include <cuda_runtime.h>
#include <cuda_bf16.h>

using ull = unsigned long long;

// ---- packed f32x2 helpers (sm_100+ PTX; ptxas never auto-fuses these) ----
__device__ __forceinline__ ull pack2(float lo, float hi) {
    ull r;
    asm("mov.b64 %0, {%1, %2};" : "=l"(r)
        : "r"(__float_as_uint(lo)), "r"(__float_as_uint(hi)));
    return r;
}
__device__ __forceinline__ void unpack2(ull v, float& lo, float& hi) {
    unsigned a, b;
    asm("mov.b64 {%0, %1}, %2;" : "=r"(a), "=r"(b) : "l"(v));
    lo = __uint_as_float(a); hi = __uint_as_float(b);
}
__device__ __forceinline__ ull ffma2(ull a, ull b, ull c) {
    ull d; asm("fma.rn.f32x2 %0, %1, %2, %3;" : "=l"(d) : "l"(a), "l"(b), "l"(c));
    return d;
}
__device__ __forceinline__ ull fmul2(ull a, ull b) {
    ull d; asm("mul.rn.f32x2 %0, %1, %2;" : "=l"(d) : "l"(a), "l"(b));
    return d;
}
__device__ __forceinline__ ull fadd2(ull a, ull b) {
    ull d; asm("add.rn.f32x2 %0, %1, %2;" : "=l"(d) : "l"(a), "l"(b));
    return d;
}

__global__ __launch_bounds__(256, 4)
void quan2d_kernel(const float2* __restrict__ x2,
                   const float* __restrict__ w,
                   float4* __restrict__ out4)
{
    __shared__ ull grp[8], grn[8];   // packed {r,r}, {-r,-r}, r = tan(theta/2)

    const int tid  = threadIdx.x;
    const int img0 = blockIdx.x * 2;

    if (tid < 8) {
        float sv, cv;
        sincosf(w[tid] * 0.5f, &sv, &cv);
        float r = __fdividef(sv, cv);   // global cosine factors cancel in <Z> ratio
        grp[tid] = pack2(r, r);
        grn[tid] = pack2(-r, -r);
    }

    // Patch tid = (ph, pw): rows 2ph..2ph+3, cols 2pw..2pw+3 of the zero-padded
    // 34x34 image. Direct-LDG gather: 16 batched LDG.64 (no smem tile, no barrier
    // on the data path). Row lines are shared across threads -> L1 hits.
    const int ph = tid >> 4, pw = tid & 15;
    const bool pwok = (pw < 15);
    const int  offb = pwok ? 1 : 0;          // second float2 of the row (cols c0+2,c0+3)

    // float2 indexing: image i, row r, pair q -> i*512 + r*16 + q
    const float2* p0base = x2 + img0 * 512 + pw;
    const float2* p1base = p0base + 512;

    ull a[16];
#pragma unroll
    for (int dr = 0; dr < 4; ++dr) {
        const int rr  = 0 /*2*ph*/ + dr;     // placeholder; real rr below
        (void)rr;
    }
#pragma unroll
    for (int dr = 0; dr < 4; ++dr) {
        int rr   = ph * 2 + dr;
        bool rok = (dr < 2) || (rr < 32);    // only ph==15, dr>=2 go out of bounds
        int rrc  = (dr < 2) ? rr : min(rr, 31);
        const float2* p0 = p0base + rrc * 16;
        const float2* p1 = p1base + rrc * 16;
        float2 a0 = p0[0],    a1 = p1[0];
        float2 b0 = p0[offb], b1 = p1[offb];
        if (!rok)          { a0.x = 0.f; a0.y = 0.f; a1.x = 0.f; a1.y = 0.f; }
        if (!rok || !pwok) { b0.x = 0.f; b0.y = 0.f; b1.x = 0.f; b1.y = 0.f; }
        a[dr * 4 + 0] = pack2(a0.x, a1.x);
        a[dr * 4 + 1] = pack2(a0.y, a1.y);
        a[dr * 4 + 2] = pack2(b0.x, b1.x);
        a[dr * 4 + 3] = pack2(b0.y, b1.y);
    }

    __syncthreads();   // constants ready; overlaps the in-flight LDGs

    // RY (tangent form, cosine deferred): new0 = t0 - r*t1 ; new1 = r*t0 + t1
    auto ry = [&](int m, int gi) {
        ull r2  = grp[gi];
        ull nr2 = grn[gi];
#pragma unroll
        for (int j = 0; j < 16; ++j) {
            if (j & m) continue;
            ull t0 = a[j], t1 = a[j | m];
            a[j]     = ffma2(nr2, t1, t0);
            a[j | m] = ffma2(r2,  t0, t1);
        }
    };
    // CNOT = compile-time register permutation (free)
    auto cnot = [&](int cb, int tb) {
#pragma unroll
        for (int j = 0; j < 16; ++j)
            if ((j & cb) && !(j & tb)) { ull t = a[j]; a[j] = a[j | tb]; a[j | tb] = t; }
    };

    ry(8, 0); ry(4, 1); ry(2, 2); ry(1, 3);
    cnot(8, 4); cnot(4, 2); cnot(2, 1); cnot(1, 8);
    ry(8, 4); ry(4, 5); ry(2, 6); ry(1, 7);

    // Group sums of squares:
    //   G[g] = sum a[j]^2, j with (bit3,bit2) = g   (j = g*4 + k)
    //   H[g] = sum a[j]^2, j with (bit1,bit0) = g   (j = k*4 + g)
    ull G[4], H[4];
#pragma unroll
    for (int g = 0; g < 4; ++g) {
        ull acc = fmul2(a[g * 4], a[g * 4]);
#pragma unroll
        for (int k = 1; k < 4; ++k) acc = ffma2(a[g * 4 + k], a[g * 4 + k], acc);
        G[g] = acc;
        ull acc2 = fmul2(a[g], a[g]);
#pragma unroll
        for (int k = 1; k < 4; ++k) acc2 = ffma2(a[k * 4 + g], a[k * 4 + g], acc2);
        H[g] = acc2;
    }
    ull nrm2 = fadd2(fadd2(G[0], G[1]), fadd2(G[2], G[3]));
    ull s0p = fadd2(G[2], G[3]);   // wire0 (bit3 set)
    ull s1p = fadd2(G[1], G[3]);   // wire1 (bit2 set)
    ull s2p = fadd2(H[2], H[3]);   // wire2 (bit1 set)
    ull s3p = fadd2(H[1], H[3]);   // wire3 (bit0 set)

    // <Z_w> = 1 - 2*s_w/nrm
    float n0, n1;
    unpack2(nrm2, n0, n1);
    ull m2inv = pack2(__fdividef(-2.0f, n0), __fdividef(-2.0f, n1));
    ull ones  = pack2(1.0f, 1.0f);

    ull z0 = ffma2(s0p, m2inv, ones);
    ull z1 = ffma2(s1p, m2inv, ones);
    ull z2 = ffma2(s2p, m2inv, ones);
    ull z3 = ffma2(s3p, m2inv, ones);

    float4 o0, o1;
    unpack2(z0, o0.x, o1.x);
    unpack2(z1, o0.y, o1.y);
    unpack2(z2, o0.z, o1.z);
    unpack2(z3, o0.w, o1.w);

    // out[img, p*4 + w] with p = tid -> coalesced float4 stores
    out4[img0 * 256 + tid]       = o0;
    out4[(img0 + 1) * 256 + tid] = o1;
}

extern "C" void kernel_launch(void* const* d_in, const int* in_sizes, int n_in,
                              void* d_out, int out_size)
{
    const float* x = (const float*)d_in[0];
    const float* w = (const float*)d_in[1];
    if (n_in >= 2 && in_sizes[0] == 8) {   // defensive input-order resolution
        x = (const float*)d_in[1];
        w = (const float*)d_in[0];
    }
    quan2d_kernel<<<4096, 256>>>((const float2*)x, w, (float4*)d_out);
}